// round 1
// baseline (speedup 1.0000x reference)
#include <cuda_runtime.h>
#include <cuda_bf16.h>

// Problem constants (fixed by reference setup_inputs)
#define B_  4
#define N_  64
#define HW_ 512   // H == W == 512

// Scratch: normalized per-label gaussians. [b][n][coord]
__device__ float g_gx[B_ * N_ * HW_];
__device__ float g_gy[B_ * N_ * HW_];

// ---------------------------------------------------------------------------
// Kernel 1: build normalized 1-D gaussians.
// grid (B*N, 2): blockIdx.x = b*N+n, blockIdx.y = axis (0->x, 1->y)
// blockDim.x = 512 (one thread per coordinate)
// ---------------------------------------------------------------------------
__global__ void prep_gaussians(const float* __restrict__ labels,
                               const float* __restrict__ sigma_p) {
    const int bn   = blockIdx.x;          // 0..255
    const int axis = blockIdx.y;          // 0 = x (gx), 1 = y (gy)
    const int t    = threadIdx.x;         // 0..511

    const float sigma = sigma_p[0];
    const float inv   = 1.0f / (2.0f * sigma * sigma);
    const float l     = labels[bn * 2 + axis];

    float d = (float)t - l;
    float e = __expf(-d * d * inv);

    // block reduction (512 threads = 16 warps)
    __shared__ float warp_sums[16];
    float s = e;
    #pragma unroll
    for (int off = 16; off > 0; off >>= 1)
        s += __shfl_xor_sync(0xFFFFFFFFu, s, off);
    const int lane = t & 31, wid = t >> 5;
    if (lane == 0) warp_sums[wid] = s;
    __syncthreads();
    if (wid == 0) {
        float v = (lane < 16) ? warp_sums[lane] : 0.0f;
        #pragma unroll
        for (int off = 8; off > 0; off >>= 1)
            v += __shfl_xor_sync(0xFFFFFFFFu, v, off);
        if (lane == 0) warp_sums[0] = v;
    }
    __syncthreads();
    const float total = warp_sums[0];

    float* out = (axis == 0) ? g_gx : g_gy;
    out[bn * HW_ + t] = e / total;
}

// ---------------------------------------------------------------------------
// Kernel 2: density[b][h][w] = sum_n gy[b][n][h] * gx[b][n][w]
// 64x64 output tile per block, 16x16 threads, 4x4 register blocking.
// grid (W/64, H/64, B) = (8, 8, 4)
// ---------------------------------------------------------------------------
__global__ __launch_bounds__(256) void density_rank64(float* __restrict__ out) {
    const int b  = blockIdx.z;
    const int h0 = blockIdx.y * 64;
    const int w0 = blockIdx.x * 64;
    const int tx = threadIdx.x;  // 0..15
    const int ty = threadIdx.y;  // 0..15
    const int tid = ty * 16 + tx;

    // sgy[n*64 + hh], sgx[n*64 + ww] : 16 KB each
    __shared__ float sgy[N_ * 64];
    __shared__ float sgx[N_ * 64];

    // cooperative load: 4096 floats each, 16 per thread
    {
        const float* gy_base = g_gy + (b * N_) * HW_;
        const float* gx_base = g_gx + (b * N_) * HW_;
        #pragma unroll
        for (int k = 0; k < 16; k++) {
            int idx = tid + k * 256;       // 0..4095
            int n  = idx >> 6;
            int c  = idx & 63;
            sgy[idx] = gy_base[n * HW_ + h0 + c];
            sgx[idx] = gx_base[n * HW_ + w0 + c];
        }
    }
    __syncthreads();

    float acc[4][4];
    #pragma unroll
    for (int i = 0; i < 4; i++)
        #pragma unroll
        for (int j = 0; j < 4; j++)
            acc[i][j] = 0.0f;

    #pragma unroll 8
    for (int n = 0; n < N_; n++) {
        float4 a  = *reinterpret_cast<const float4*>(&sgy[n * 64 + ty * 4]);
        float4 bx = *reinterpret_cast<const float4*>(&sgx[n * 64 + tx * 4]);
        acc[0][0] += a.x * bx.x; acc[0][1] += a.x * bx.y; acc[0][2] += a.x * bx.z; acc[0][3] += a.x * bx.w;
        acc[1][0] += a.y * bx.x; acc[1][1] += a.y * bx.y; acc[1][2] += a.y * bx.z; acc[1][3] += a.y * bx.w;
        acc[2][0] += a.z * bx.x; acc[2][1] += a.z * bx.y; acc[2][2] += a.z * bx.z; acc[2][3] += a.z * bx.w;
        acc[3][0] += a.w * bx.x; acc[3][1] += a.w * bx.y; acc[3][2] += a.w * bx.z; acc[3][3] += a.w * bx.w;
    }

    // store: rows h0 + ty*4 + i, cols w0 + tx*4 .. +3 (float4, coalesced)
    float* ob = out + ((size_t)b * HW_ + h0) * HW_ + w0;
    #pragma unroll
    for (int i = 0; i < 4; i++) {
        float4 v = make_float4(acc[i][0], acc[i][1], acc[i][2], acc[i][3]);
        *reinterpret_cast<float4*>(&ob[(ty * 4 + i) * (size_t)HW_ + tx * 4]) = v;
    }
}

extern "C" void kernel_launch(void* const* d_in, const int* in_sizes, int n_in,
                              void* d_out, int out_size) {
    // d_in[0]: batch_images (4,3,512,512) f32 — unused (shape only)
    // d_in[1]: batch_labels (4,64,2) f32
    // d_in[2]: sigma scalar f32
    const float* labels = (const float*)d_in[1];
    const float* sigma  = (const float*)d_in[2];
    float* out = (float*)d_out;

    dim3 g1(B_ * N_, 2);
    prep_gaussians<<<g1, 512>>>(labels, sigma);

    dim3 g2(HW_ / 64, HW_ / 64, B_);
    dim3 b2(16, 16);
    density_rank64<<<g2, b2>>>(out);
}

// round 2
// speedup vs baseline: 1.1045x; 1.1045x over previous
#include <cuda_runtime.h>
#include <cuda_bf16.h>

// Fixed problem shape
#define B_   4
#define N_   64
#define HW_  512
#define TH_  128   // tile rows (h)
#define TW_  64    // tile cols (w)

// Fused kernel: per 128x64 output tile, compute normalization sums (truncated
// gaussian window), build normalized 1-D gaussians in smem, then rank-64 GEMM.
// grid (8, 4, 4) = 128 blocks, 512 threads. smem = 48KB exactly.
__global__ __launch_bounds__(512) void density_fused(
    const float* __restrict__ labels,   // (B, N, 2)
    const float* __restrict__ sigma_p,  // scalar
    float* __restrict__ out)            // (B, 1, 512, 512)
{
    __shared__ float sgy[N_ * TH_];   // 32 KB : gy * inv_sy * inv_sx
    __shared__ float sgx[N_ * TW_];   // 16 KB : raw gx (sums staged here first)

    const int b  = blockIdx.z;
    const int h0 = blockIdx.y * TH_;
    const int w0 = blockIdx.x * TW_;
    const int t  = threadIdx.x;        // 0..511

    const float sigma = sigma_p[0];
    const float inv   = 1.0f / (2.0f * sigma * sigma);
    const float R     = 6.5f * sigma;  // truncation radius: e^{-21} tail
    const float* lab  = labels + (b * N_) * 2;

    // ---------------- Phase A: inverse sums for 128 (n,axis) pairs ----------
    // 4 threads per pair. Staged into sgx[axis*64 + n].
    {
        const int j    = t & 3;
        const int p    = t >> 2;       // 0..127
        const int n    = p & 63;
        const int axis = p >> 6;       // 0 = x, 1 = y

        const float l  = lab[n * 2 + axis];
        int lo = (int)ceilf(l - R);  if (lo < 0) lo = 0;
        int hi = (int)floorf(l + R); if (hi > HW_ - 1) hi = HW_ - 1;

        float s = 0.0f;
        for (int i = lo + j; i <= hi; i += 4) {
            float d = (float)i - l;
            s += __expf(-d * d * inv);
        }
        s += __shfl_xor_sync(0xFFFFFFFFu, s, 1);
        s += __shfl_xor_sync(0xFFFFFFFFu, s, 2);
        if (j == 0) sgx[axis * N_ + n] = 1.0f / s;   // inv_sx at [n], inv_sy at [64+n]
    }
    __syncthreads();

    // ---------------- Phase B: tile gaussians -------------------------------
    // 12288 values, 24 per thread. Compute into registers first (sums live in
    // sgx), then sync, then write.
    float v[24];
    #pragma unroll
    for (int k = 0; k < 24; k++) {
        int idx = t + k * 512;
        if (idx < N_ * TH_) {                 // gy region
            int n = idx >> 7;                 // /128
            int c = idx & (TH_ - 1);
            float l = lab[n * 2 + 1];         // y label
            float d = (float)(h0 + c) - l;
            v[k] = __expf(-d * d * inv) * sgx[N_ + n] * sgx[n];  // inv_sy * inv_sx
        } else {                              // gx region (raw exp)
            int i2 = idx - N_ * TH_;
            int n = i2 >> 6;                  // /64
            int c = i2 & (TW_ - 1);
            float l = lab[n * 2 + 0];         // x label
            float d = (float)(w0 + c) - l;
            v[k] = __expf(-d * d * inv);
        }
    }
    __syncthreads();
    #pragma unroll
    for (int k = 0; k < 24; k++) {
        int idx = t + k * 512;
        if (idx < N_ * TH_) sgy[idx] = v[k];
        else                sgx[idx - N_ * TH_] = v[k];
    }
    __syncthreads();

    // ---------------- Phase C: rank-64 outer-product accumulation -----------
    const int tx = t & 15;    // 0..15  -> 4 cols each
    const int ty = t >> 4;    // 0..31  -> 4 rows each

    float acc[4][4];
    #pragma unroll
    for (int i = 0; i < 4; i++)
        #pragma unroll
        for (int j = 0; j < 4; j++)
            acc[i][j] = 0.0f;

    #pragma unroll 8
    for (int n = 0; n < N_; n++) {
        float4 a  = *reinterpret_cast<const float4*>(&sgy[n * TH_ + ty * 4]);
        float4 bx = *reinterpret_cast<const float4*>(&sgx[n * TW_ + tx * 4]);
        acc[0][0] += a.x * bx.x; acc[0][1] += a.x * bx.y; acc[0][2] += a.x * bx.z; acc[0][3] += a.x * bx.w;
        acc[1][0] += a.y * bx.x; acc[1][1] += a.y * bx.y; acc[1][2] += a.y * bx.z; acc[1][3] += a.y * bx.w;
        acc[2][0] += a.z * bx.x; acc[2][1] += a.z * bx.y; acc[2][2] += a.z * bx.z; acc[2][3] += a.z * bx.w;
        acc[3][0] += a.w * bx.x; acc[3][1] += a.w * bx.y; acc[3][2] += a.w * bx.z; acc[3][3] += a.w * bx.w;
    }

    float* ob = out + ((size_t)b * HW_ + h0 + ty * 4) * HW_ + w0 + tx * 4;
    #pragma unroll
    for (int i = 0; i < 4; i++) {
        float4 r = make_float4(acc[i][0], acc[i][1], acc[i][2], acc[i][3]);
        *reinterpret_cast<float4*>(&ob[i * (size_t)HW_]) = r;
    }
}

extern "C" void kernel_launch(void* const* d_in, const int* in_sizes, int n_in,
                              void* d_out, int out_size) {
    // d_in[0]: batch_images (unused, shape only)
    // d_in[1]: batch_labels (4,64,2) f32
    // d_in[2]: sigma scalar f32
    const float* labels = (const float*)d_in[1];
    const float* sigma  = (const float*)d_in[2];
    float* out = (float*)d_out;

    dim3 grid(HW_ / TW_, HW_ / TH_, B_);   // (8, 4, 4)
    density_fused<<<grid, 512>>>(labels, sigma, out);
}

// round 4
// speedup vs baseline: 1.4535x; 1.3160x over previous
#include <cuda_runtime.h>
#include <cuda_bf16.h>

// Fixed problem shape
#define B_    4
#define N_    64
#define HW_   512
#define TH_   128    // tile rows (h)
#define TW_   64     // tile cols (w)
#define MAXC  16     // labels per chunk (== #warps)

// Sparse fused kernel: per 128x64 tile, find labels whose +-R window overlaps
// the tile, build their normalized windowed 1-D gaussians, accumulate rank-nc.
// grid (8, 4, 4) = 128 blocks (one wave on 148 SMs), 512 threads.
__global__ __launch_bounds__(512) void density_sparse(
    const float* __restrict__ labels,   // (B, N, 2)
    const float* __restrict__ sigma_p,  // scalar
    float* __restrict__ out)            // (B, 1, 512, 512)
{
    // 16B-aligned first: these are read with LDS.128
    __shared__ __align__(16) float    s_gy[MAXC][TH_];   // gy * inv  (8 KB)
    __shared__ __align__(16) float    s_gx[MAXC][TW_];   // raw gx    (4 KB)
    __shared__ __align__(16) float    s_lab[N_ * 2];
    __shared__ float    s_inv[MAXC];           // 1/(sum_x * sum_y)
    __shared__ int      s_list[N_];
    __shared__ int      s_cnt;
    __shared__ unsigned s_mask[2];

    const int b  = blockIdx.z;
    const int h0 = blockIdx.y * TH_;
    const int w0 = blockIdx.x * TW_;
    const int t  = threadIdx.x;                // 0..511

    const float sigma = sigma_p[0];
    const float inv2  = 1.0f / (2.0f * sigma * sigma);
    const float R     = 6.5f * sigma;          // e^{-21} truncation

    // load labels for this batch
    if (t < N_ * 2) s_lab[t] = labels[b * N_ * 2 + t];
    __syncthreads();

    // -------- active-label compaction (warps 0,1: one label per thread) -----
    bool act = false;
    if (t < N_) {
        float lx = s_lab[2 * t];
        float ly = s_lab[2 * t + 1];
        act = (lx >= (float)w0 - R) && (lx <= (float)(w0 + TW_ - 1) + R) &&
              (ly >= (float)h0 - R) && (ly <= (float)(h0 + TH_ - 1) + R);
        unsigned m = __ballot_sync(0xFFFFFFFFu, act);
        if ((t & 31) == 0) s_mask[t >> 5] = m;
    }
    __syncthreads();
    if (t < N_) {
        int w = t >> 5;
        if (act) {
            int pos = __popc(s_mask[w] & ((1u << (t & 31)) - 1u))
                    + (w ? __popc(s_mask[0]) : 0);
            s_list[pos] = t;
        }
        if (t == 0) s_cnt = __popc(s_mask[0]) + __popc(s_mask[1]);
    }
    __syncthreads();
    const int cnt = s_cnt;

    float acc[4][4];
    #pragma unroll
    for (int i = 0; i < 4; i++)
        #pragma unroll
        for (int j = 0; j < 4; j++) acc[i][j] = 0.0f;

    const int tx = t & 15;     // 4 cols each
    const int ty = t >> 4;     // 4 rows each

    for (int c0 = 0; c0 < cnt; c0 += MAXC) {
        const int nc = min(MAXC, cnt - c0);

        // ---- normalization sums: warp li handles chunk label li ------------
        // lanes 0-15 -> x axis, lanes 16-31 -> y axis, 16-lane strided sum
        {
            const int li   = t >> 5;           // warp id 0..15
            const int axis = (t >> 4) & 1;
            const int j    = t & 15;
            if (li < nc) {
                const int n   = s_list[c0 + li];
                const float l = s_lab[2 * n + axis];
                int lo = (int)ceilf(l - R);  if (lo < 0) lo = 0;
                int hi = (int)floorf(l + R); if (hi > HW_ - 1) hi = HW_ - 1;
                float s = 0.0f;
                for (int i = lo + j; i <= hi; i += 16) {
                    float d = (float)i - l;
                    s += __expf(-d * d * inv2);
                }
                s += __shfl_xor_sync(0xFFFFFFFFu, s, 1);
                s += __shfl_xor_sync(0xFFFFFFFFu, s, 2);
                s += __shfl_xor_sync(0xFFFFFFFFu, s, 4);
                s += __shfl_xor_sync(0xFFFFFFFFu, s, 8);
                // lane 0 has x-sum, lane 16 has y-sum
                float sy = __shfl_sync(0xFFFFFFFFu, s, 16);
                if ((t & 31) == 0) s_inv[li] = 1.0f / (s * sy);
            }
        }
        __syncthreads();

        // ---- windowed gaussian values (gy scaled by inv, gx raw) ----------
        for (int idx = t; idx < nc * (TH_ + TW_); idx += 512) {
            const int li = idx / (TH_ + TW_);
            const int r  = idx - li * (TH_ + TW_);
            const int n  = s_list[c0 + li];
            if (r < TH_) {
                float l = s_lab[2 * n + 1];
                float d = (float)(h0 + r) - l;
                s_gy[li][r] = (fabsf(d) <= R) ? __expf(-d * d * inv2) * s_inv[li]
                                              : 0.0f;
            } else {
                int c = r - TH_;
                float l = s_lab[2 * n];
                float d = (float)(w0 + c) - l;
                s_gx[li][c] = (fabsf(d) <= R) ? __expf(-d * d * inv2) : 0.0f;
            }
        }
        __syncthreads();

        // ---- sparse rank-nc outer-product accumulation --------------------
        #pragma unroll 4
        for (int li = 0; li < nc; li++) {
            float4 a  = *reinterpret_cast<const float4*>(&s_gy[li][ty * 4]);
            float4 bx = *reinterpret_cast<const float4*>(&s_gx[li][tx * 4]);
            acc[0][0] += a.x * bx.x; acc[0][1] += a.x * bx.y; acc[0][2] += a.x * bx.z; acc[0][3] += a.x * bx.w;
            acc[1][0] += a.y * bx.x; acc[1][1] += a.y * bx.y; acc[1][2] += a.y * bx.z; acc[1][3] += a.y * bx.w;
            acc[2][0] += a.z * bx.x; acc[2][1] += a.z * bx.y; acc[2][2] += a.z * bx.z; acc[2][3] += a.z * bx.w;
            acc[3][0] += a.w * bx.x; acc[3][1] += a.w * bx.y; acc[3][2] += a.w * bx.z; acc[3][3] += a.w * bx.w;
        }
        __syncthreads();
    }

    // ---- store (zeros where no label overlaps) ----------------------------
    float* ob = out + ((size_t)b * HW_ + h0 + ty * 4) * HW_ + w0 + tx * 4;
    #pragma unroll
    for (int i = 0; i < 4; i++) {
        float4 r = make_float4(acc[i][0], acc[i][1], acc[i][2], acc[i][3]);
        *reinterpret_cast<float4*>(&ob[i * (size_t)HW_]) = r;
    }
}

extern "C" void kernel_launch(void* const* d_in, const int* in_sizes, int n_in,
                              void* d_out, int out_size) {
    // d_in[0]: batch_images (unused, shape only)
    // d_in[1]: batch_labels (4,64,2) f32
    // d_in[2]: sigma scalar f32
    const float* labels = (const float*)d_in[1];
    const float* sigma  = (const float*)d_in[2];
    float* out = (float*)d_out;

    dim3 grid(HW_ / TW_, HW_ / TH_, B_);   // (8, 4, 4)
    density_sparse<<<grid, 512>>>(labels, sigma, out);
}

// round 5
// speedup vs baseline: 1.5333x; 1.0549x over previous
#include <cuda_runtime.h>
#include <cuda_bf16.h>

// Fixed problem shape
#define B_    4
#define N_    64
#define HW_   512
#define T_    64     // tile 64x64
#define MAXC  8      // labels per chunk (== #warps)

// Sparse fused kernel, latency-optimized:
//  - 256 blocks (one per 64x64 tile), 256 threads -> ~2 blocks/SM overlap
//  - analytic gaussian normalization (sigma*sqrt(2pi)) for unclipped labels
//  - normalization applied in the accumulate phase -> one sync between
//    setup and accumulation per chunk
__global__ __launch_bounds__(256) void density_sparse2(
    const float* __restrict__ labels,   // (B, N, 2)
    const float* __restrict__ sigma_p,  // scalar
    float* __restrict__ out)            // (B, 1, 512, 512)
{
    __shared__ __align__(16) float s_gy[MAXC][T_];   // raw gy (2 KB)
    __shared__ __align__(16) float s_gx[MAXC][T_];   // raw gx (2 KB)
    __shared__ __align__(16) float s_lab[N_ * 2];
    __shared__ float    s_inv[MAXC];                 // 1/(sum_x*sum_y)
    __shared__ int      s_list[N_];
    __shared__ int      s_cnt;
    __shared__ unsigned s_mask[2];

    const int b  = blockIdx.z;
    const int h0 = blockIdx.y * T_;
    const int w0 = blockIdx.x * T_;
    const int t  = threadIdx.x;                 // 0..255

    const float sigma  = sigma_p[0];
    const float inv2   = 1.0f / (2.0f * sigma * sigma);
    const float R      = 6.5f * sigma;          // e^{-21} truncation
    const float s_an   = sigma * 2.5066282746310002f;   // sigma*sqrt(2*pi)
    const float inv_an = 1.0f / (s_an * s_an);

    if (t < N_ * 2) s_lab[t] = labels[b * N_ * 2 + t];
    __syncthreads();

    // -------- active-label compaction (threads 0..63) -----------------------
    bool act = false;
    if (t < N_) {
        float lx = s_lab[2 * t];
        float ly = s_lab[2 * t + 1];
        act = (lx >= (float)w0 - R) && (lx <= (float)(w0 + T_ - 1) + R) &&
              (ly >= (float)h0 - R) && (ly <= (float)(h0 + T_ - 1) + R);
        unsigned m = __ballot_sync(0xFFFFFFFFu, act);
        if ((t & 31) == 0) s_mask[t >> 5] = m;
    }
    __syncthreads();
    if (t < N_) {
        int w = t >> 5;
        if (act) {
            int pos = __popc(s_mask[w] & ((1u << (t & 31)) - 1u))
                    + (w ? __popc(s_mask[0]) : 0);
            s_list[pos] = t;
        }
        if (t == 0) s_cnt = __popc(s_mask[0]) + __popc(s_mask[1]);
    }
    __syncthreads();
    const int cnt = s_cnt;

    float acc[4][4];
    #pragma unroll
    for (int i = 0; i < 4; i++)
        #pragma unroll
        for (int j = 0; j < 4; j++) acc[i][j] = 0.0f;

    const int tx = t & 15;      // 4 cols each
    const int ty = t >> 4;      // 4 rows each (0..15)
    const int wi   = t >> 5;    // warp id 0..7
    const int lane = t & 31;

    for (int c0 = 0; c0 < cnt; c0 += MAXC) {
        const int nc = min(MAXC, cnt - c0);

        // ---- raw windowed gaussian values (unscaled), 128 elems per label --
        for (int idx = t; idx < nc * (2 * T_); idx += 256) {
            const int li = idx >> 7;
            const int r  = idx & 127;
            const int n  = s_list[c0 + li];
            if (r < T_) {
                float l = s_lab[2 * n + 1];
                float d = (float)(h0 + r) - l;
                s_gy[li][r] = (fabsf(d) <= R) ? __expf(-d * d * inv2) : 0.0f;
            } else {
                float l = s_lab[2 * n];
                float d = (float)(w0 + (r - T_)) - l;
                s_gx[li][r - T_] = (fabsf(d) <= R) ? __expf(-d * d * inv2) : 0.0f;
            }
        }

        // ---- normalization: warp wi handles chunk label wi ------------------
        if (wi < nc) {
            const int n = s_list[c0 + wi];
            const float lx = s_lab[2 * n];
            const float ly = s_lab[2 * n + 1];
            const bool clipped = (lx < R) || (lx > 511.0f - R) ||
                                 (ly < R) || (ly > 511.0f - R);
            if (!clipped) {
                if (lane == 0) s_inv[wi] = inv_an;   // both sums analytic
            } else {
                // lanes 0-15: x axis, lanes 16-31: y axis
                const int axis = lane >> 4;
                const int j    = lane & 15;
                const float l  = axis ? ly : lx;
                float s;
                if (l >= R && l <= 511.0f - R) {
                    s = (j == 0) ? s_an : 0.0f;       // this axis unclipped
                } else {
                    int lo = (int)ceilf(l - R);  if (lo < 0) lo = 0;
                    int hi = (int)floorf(l + R); if (hi > HW_ - 1) hi = HW_ - 1;
                    s = 0.0f;
                    for (int i = lo + j; i <= hi; i += 16) {
                        float d = (float)i - l;
                        s += __expf(-d * d * inv2);
                    }
                }
                s += __shfl_xor_sync(0xFFFFFFFFu, s, 1);
                s += __shfl_xor_sync(0xFFFFFFFFu, s, 2);
                s += __shfl_xor_sync(0xFFFFFFFFu, s, 4);
                s += __shfl_xor_sync(0xFFFFFFFFu, s, 8);
                float so = __shfl_xor_sync(0xFFFFFFFFu, s, 16);
                if (lane == 0) s_inv[wi] = 1.0f / (s * so);
            }
        }
        __syncthreads();

        // ---- rank-nc outer-product accumulation (inv folded into a) --------
        #pragma unroll 4
        for (int li = 0; li < nc; li++) {
            const float inv = s_inv[li];
            float4 a  = *reinterpret_cast<const float4*>(&s_gy[li][ty * 4]);
            float4 bx = *reinterpret_cast<const float4*>(&s_gx[li][tx * 4]);
            a.x *= inv; a.y *= inv; a.z *= inv; a.w *= inv;
            acc[0][0] += a.x * bx.x; acc[0][1] += a.x * bx.y; acc[0][2] += a.x * bx.z; acc[0][3] += a.x * bx.w;
            acc[1][0] += a.y * bx.x; acc[1][1] += a.y * bx.y; acc[1][2] += a.y * bx.z; acc[1][3] += a.y * bx.w;
            acc[2][0] += a.z * bx.x; acc[2][1] += a.z * bx.y; acc[2][2] += a.z * bx.z; acc[2][3] += a.z * bx.w;
            acc[3][0] += a.w * bx.x; acc[3][1] += a.w * bx.y; acc[3][2] += a.w * bx.z; acc[3][3] += a.w * bx.w;
        }
        __syncthreads();
    }

    // ---- store (zeros where no label overlaps) ------------------------------
    float* ob = out + ((size_t)b * HW_ + h0 + ty * 4) * HW_ + w0 + tx * 4;
    #pragma unroll
    for (int i = 0; i < 4; i++) {
        float4 r = make_float4(acc[i][0], acc[i][1], acc[i][2], acc[i][3]);
        *reinterpret_cast<float4*>(&ob[i * (size_t)HW_]) = r;
    }
}

extern "C" void kernel_launch(void* const* d_in, const int* in_sizes, int n_in,
                              void* d_out, int out_size) {
    // d_in[0]: batch_images (unused, shape only)
    // d_in[1]: batch_labels (4,64,2) f32
    // d_in[2]: sigma scalar f32
    const float* labels = (const float*)d_in[1];
    const float* sigma  = (const float*)d_in[2];
    float* out = (float*)d_out;

    dim3 grid(HW_ / T_, HW_ / T_, B_);   // (8, 8, 4) = 256 blocks
    density_sparse2<<<grid, 256>>>(labels, sigma, out);
}